// round 15
// baseline (speedup 1.0000x reference)
#include <cuda_runtime.h>

#define T_STEPS 240
#define H       25
#define BLK     128

typedef unsigned long long u64;

// ---------------------------------------------------------------------------
// Packed f32x2 helpers (Blackwell)
// ---------------------------------------------------------------------------
__device__ __forceinline__ u64 pack2(float lo, float hi) {
    u64 r;
    asm("mov.b64 %0, {%1, %2};" : "=l"(r) : "f"(lo), "f"(hi));
    return r;
}
__device__ __forceinline__ float unpack_sum(u64 v) {
    float lo, hi;
    asm("mov.b64 {%0, %1}, %2;" : "=f"(lo), "=f"(hi) : "l"(v));
    return lo + hi;
}
#define UNPACK2(V, LO, HI) \
    asm("mov.b64 {%0, %1}, %2;" : "=f"(LO), "=f"(HI) : "l"(V))
#define FFMA2(acc, h, w) \
    asm("fma.rn.f32x2 %0, %1, %2, %0;" : "+l"(acc) : "l"(h), "l"(w))

// Hardware tanh (single MUFU). Sigmoid gates use PRESCALED weights (x0.5
// folded into the weight table): sigmoid(v) = fma(tanh(v_scaled), .5, .5).
__device__ __forceinline__ float tanh_ap(float x) {
    float y;
    asm("tanh.approx.f32 %0, %1;" : "=f"(y) : "f"(x));
    return y;
}
__device__ __forceinline__ float sig_ps(float v_scaled) {
    return fmaf(tanh_ap(v_scaled), 0.5f, 0.5f);
}

#define R12(M) M(0) M(1) M(2) M(3) M(4) M(5) M(6) M(7) M(8) M(9) M(10) M(11)
#define R25(M) R12(M) M(12) M(13) M(14) M(15) M(16) M(17) M(18) M(19) M(20) \
               M(21) M(22) M(23) M(24)

// h-pair double buffers (read/write alternate by step parity); pair 12 and
// the constant pair 13 are shared (rebuilt / constant each step).
#define DECL_HP(Q) u64 hpA##Q = 0, hpB##Q = 0;
#define DECL_C(J)  float c##J = 0.f;

// 14-pair MAC for one gate of unit J, weights broadcast from the smem table.
// wtab layout: u64 wtab[unit][gate][pair] with gate order {cell, i, f, o};
// pair q<12 = (w_{2q}, w_{2q+1}); pair 12 = (w_24, w_ih); pair 13 = (bias, 0).
// All offsets compile-time; all lanes read the same address (broadcast).
#define MACG(ACC, J, G, P) {                                                  \
    const ulonglong2* wp_ =                                                   \
        reinterpret_cast<const ulonglong2*>(wtab + (J) * 56 + (G) * 14);      \
    ulonglong2 w_;                                                            \
    w_ = wp_[0]; FFMA2(ACC, P##0,  w_.x); FFMA2(ACC, P##1,  w_.y);            \
    w_ = wp_[1]; FFMA2(ACC, P##2,  w_.x); FFMA2(ACC, P##3,  w_.y);            \
    w_ = wp_[2]; FFMA2(ACC, P##4,  w_.x); FFMA2(ACC, P##5,  w_.y);            \
    w_ = wp_[3]; FFMA2(ACC, P##6,  w_.x); FFMA2(ACC, P##7,  w_.y);            \
    w_ = wp_[4]; FFMA2(ACC, P##8,  w_.x); FFMA2(ACC, P##9,  w_.y);            \
    w_ = wp_[5]; FFMA2(ACC, P##10, w_.x); FFMA2(ACC, P##11, w_.y);            \
    w_ = wp_[6]; FFMA2(ACC, hp12,  w_.x); FFMA2(ACC, cp13,  w_.y); }

// One hidden unit: 4 gate MACs (cell gate first so its tanh MUFU overlaps
// the i/f/o MACs), activations, state update. STORE commits the new h.
#define UNIT_BODY(J, P, STORE) {                                              \
    u64 ag = 0, ai = 0, af = 0, ao = 0;                                       \
    MACG(ag, J, 0, P)                                                         \
    float ggv = tanh_ap(unpack_sum(ag));                                      \
    MACG(ai, J, 1, P)                                                         \
    MACG(af, J, 2, P)                                                         \
    MACG(ao, J, 3, P)                                                         \
    float ig = sig_ps(unpack_sum(ai));                                        \
    float fg = sig_ps(unpack_sum(af));                                        \
    float og = sig_ps(unpack_sum(ao));                                        \
    c##J = fmaf(fg, c##J, ig * ggv);                                          \
    float hnew = og * tanh_ap(c##J);                                          \
    STORE; }

// One timestep: read pairs P##0..P##11 (+hp12, cp13), write pairs Wr##0..11.
#define STEP(P, Wr, XV) do {                                                  \
    hp12 = pack2(h24s, (XV));                                                 \
    float hre;                                                                \
    UNIT_BODY(0,  P, hre = hnew)                                              \
    UNIT_BODY(1,  P, Wr##0  = pack2(hre, hnew))                               \
    UNIT_BODY(2,  P, hre = hnew)                                              \
    UNIT_BODY(3,  P, Wr##1  = pack2(hre, hnew))                               \
    UNIT_BODY(4,  P, hre = hnew)                                              \
    UNIT_BODY(5,  P, Wr##2  = pack2(hre, hnew))                               \
    UNIT_BODY(6,  P, hre = hnew)                                              \
    UNIT_BODY(7,  P, Wr##3  = pack2(hre, hnew))                               \
    UNIT_BODY(8,  P, hre = hnew)                                              \
    UNIT_BODY(9,  P, Wr##4  = pack2(hre, hnew))                               \
    UNIT_BODY(10, P, hre = hnew)                                              \
    UNIT_BODY(11, P, Wr##5  = pack2(hre, hnew))                               \
    UNIT_BODY(12, P, hre = hnew)                                              \
    UNIT_BODY(13, P, Wr##6  = pack2(hre, hnew))                               \
    UNIT_BODY(14, P, hre = hnew)                                              \
    UNIT_BODY(15, P, Wr##7  = pack2(hre, hnew))                               \
    UNIT_BODY(16, P, hre = hnew)                                              \
    UNIT_BODY(17, P, Wr##8  = pack2(hre, hnew))                               \
    UNIT_BODY(18, P, hre = hnew)                                              \
    UNIT_BODY(19, P, Wr##9  = pack2(hre, hnew))                               \
    UNIT_BODY(20, P, hre = hnew)                                              \
    UNIT_BODY(21, P, Wr##10 = pack2(hre, hnew))                               \
    UNIT_BODY(22, P, hre = hnew)                                              \
    UNIT_BODY(23, P, Wr##11 = pack2(hre, hnew))                               \
    UNIT_BODY(24, P, h24s = hnew)                                             \
} while (0)

__global__ void __launch_bounds__(BLK) lstm_kernel(
    const float* __restrict__ x,      // [B, T, 1]
    const float* __restrict__ W_ih,   // [4H, 1]
    const float* __restrict__ W_hh,   // [4H, H]
    const float* __restrict__ b_ih,   // [4H]
    const float* __restrict__ b_hh,   // [4H]
    const float* __restrict__ W_fc,   // [2, H]
    const float* __restrict__ b_fc,   // [2]
    float* __restrict__ out,          // [B, 2]
    int B)
{
    // Weight table: 25 units x 4 gates x 14 u64 pairs = 11200 B. All loop
    // reads are warp-uniform broadcasts (1 crossbar cycle each).
    __shared__ __align__(16) u64 wtab[25 * 4 * 14];

    const int tid = threadIdx.x;

    // ---- one-time staging (gate order: cell, i, f, o; i/f/o prescaled) ----
    for (int i = tid; i < 25 * 4 * 14; i += BLK) {
        int j = i / 56, rem = i % 56, g = rem / 14, q = rem % 14;
        int ptg = (g == 0) ? 2 : ((g == 3) ? 3 : g - 1);   // PyTorch gate row
        int row = ptg * H + j;
        float s = (g == 0) ? 1.f : 0.5f;
        float lo, hi;
        if (q < 12) {
            lo = s * W_hh[row * H + 2 * q];
            hi = s * W_hh[row * H + 2 * q + 1];
        } else if (q == 12) {
            lo = s * W_hh[row * H + 24];
            hi = s * W_ih[row];
        } else {
            lo = s * (b_ih[row] + b_hh[row]);
            hi = 0.f;
        }
        wtab[i] = pack2(lo, hi);
    }
    __syncthreads();

    const int  bRaw  = blockIdx.x * BLK + tid;
    const bool valid = (bRaw < B);
    const int  b     = valid ? bRaw : (B - 1);

    // ---- per-thread state: all named scalars (cannot be demoted) ----
    R12(DECL_HP)                    // hpA0..11, hpB0..11
    u64 hp12 = 0;                   // (h24, x_t), rebuilt each step
    const u64 cp13 = pack2(1.f, 0.f);  // bias rider pair
    R25(DECL_C)                     // c0..c24
    float h24s = 0.f;

    const float2* xp = reinterpret_cast<const float2*>(x + (size_t)b * T_STEPS);

#pragma unroll 1
    for (int t2 = 0; t2 < T_STEPS / 2; t2++) {
        float2 xv = __ldg(xp + t2);
        STEP(hpA, hpB, xv.x);       // even step: read A, write B
        STEP(hpB, hpA, xv.y);       // odd step: read B, write A
    }
    // 240 steps: final h pairs in hpA, final h24 in h24s.

    // ---- FC head (per-thread scalar; all W_fc reads are broadcasts) ----
    float l0 = __ldg(&b_fc[0]), l1 = __ldg(&b_fc[1]);
#define FCQ(Q) {                                                              \
    float lo_, hi_;                                                           \
    UNPACK2(hpA##Q, lo_, hi_);                                                \
    l0 = fmaf(lo_, __ldg(&W_fc[2 * (Q)]),         l0);                        \
    l0 = fmaf(hi_, __ldg(&W_fc[2 * (Q) + 1]),     l0);                        \
    l1 = fmaf(lo_, __ldg(&W_fc[H + 2 * (Q)]),     l1);                        \
    l1 = fmaf(hi_, __ldg(&W_fc[H + 2 * (Q) + 1]), l1); }
    R12(FCQ)
    l0 = fmaf(h24s, __ldg(&W_fc[24]),     l0);
    l1 = fmaf(h24s, __ldg(&W_fc[H + 24]), l1);

    if (valid) {
        out[(size_t)bRaw * 2 + 0] = l0;
        out[(size_t)bRaw * 2 + 1] = l1;
    }
}

extern "C" void kernel_launch(void* const* d_in, const int* in_sizes, int n_in,
                              void* d_out, int out_size) {
    const float* x    = (const float*)d_in[0];
    const float* W_ih = (const float*)d_in[1];
    const float* W_hh = (const float*)d_in[2];
    const float* b_ih = (const float*)d_in[3];
    const float* b_hh = (const float*)d_in[4];
    const float* W_fc = (const float*)d_in[5];
    const float* b_fc = (const float*)d_in[6];

    int B = in_sizes[0] / T_STEPS;          // x is [B, T, 1]
    int blocks = (B + BLK - 1) / BLK;       // one thread per batch element

    lstm_kernel<<<blocks, BLK>>>(x, W_ih, W_hh, b_ih, b_hh, W_fc, b_fc,
                                 (float*)d_out, B);
}

// round 16
// speedup vs baseline: 12.4785x; 12.4785x over previous
#include <cuda_runtime.h>

#define T_STEPS 240
#define H       25
#define BLK     128
#define WPB     (BLK / 32)

typedef unsigned long long u64;

// ---------------------------------------------------------------------------
// Packed f32x2 helpers (Blackwell)
// ---------------------------------------------------------------------------
__device__ __forceinline__ u64 pack2(float lo, float hi) {
    u64 r;
    asm("mov.b64 %0, {%1, %2};" : "=l"(r) : "f"(lo), "f"(hi));
    return r;
}
__device__ __forceinline__ float unpack_sum(u64 v) {
    float lo, hi;
    asm("mov.b64 {%0, %1}, %2;" : "=f"(lo), "=f"(hi) : "l"(v));
    return lo + hi;
}
#define FFMA2(acc, h, w) \
    asm("fma.rn.f32x2 %0, %1, %2, %0;" : "+l"(acc) : "l"(h), "l"(w))

// ---------------------------------------------------------------------------
// Hardware tanh (single MUFU). Sigmoid gates use PRESCALED weights (x0.5
// folded into W/bias at load): sigmoid(v) = fma(tanh(v_scaled), .5, .5).
// ---------------------------------------------------------------------------
__device__ __forceinline__ float tanh_ap(float x) {
    float y;
    asm("tanh.approx.f32 %0, %1;" : "=f"(y) : "f"(x));
    return y;
}
__device__ __forceinline__ float sig_ps(float v_scaled) {
    return fmaf(tanh_ap(v_scaled), 0.5f, 0.5f);
}

// Packed-k indices 0..12 (k pairs (0,1)..(24,25); k=25 padded to 0)
#define R13(M) M(0) M(1) M(2) M(3) M(4) M(5) M(6) M(7) M(8) M(9) M(10) M(11) M(12)

#define DECL_WP(Q) u64 wi##Q, wf##Q, wg##Q, wo##Q;

// Gate scale: i,f,o rows x0.5 (sigmoid prescale, exact); g row x1.
#define LOAD_WP(Q) {                                                          \
    const int k0 = 2 * (Q), k1 = 2 * (Q) + 1;                                 \
    float a, b;                                                               \
    a = (lv && k0 < H) ? 0.5f * __ldg(&W_hh[(0 * H + jc) * H + k0]) : 0.f;    \
    b = (lv && k1 < H) ? 0.5f * __ldg(&W_hh[(0 * H + jc) * H + k1]) : 0.f;    \
    wi##Q = pack2(a, b);                                                      \
    a = (lv && k0 < H) ? 0.5f * __ldg(&W_hh[(1 * H + jc) * H + k0]) : 0.f;    \
    b = (lv && k1 < H) ? 0.5f * __ldg(&W_hh[(1 * H + jc) * H + k1]) : 0.f;    \
    wf##Q = pack2(a, b);                                                      \
    a = (lv && k0 < H) ? __ldg(&W_hh[(2 * H + jc) * H + k0]) : 0.f;           \
    b = (lv && k1 < H) ? __ldg(&W_hh[(2 * H + jc) * H + k1]) : 0.f;           \
    wg##Q = pack2(a, b);                                                      \
    a = (lv && k0 < H) ? 0.5f * __ldg(&W_hh[(3 * H + jc) * H + k0]) : 0.f;    \
    b = (lv && k1 < H) ? 0.5f * __ldg(&W_hh[(3 * H + jc) * H + k1]) : 0.f;    \
    wo##Q = pack2(a, b);                                                      \
}

// Full 13-pair MAC for one accumulator from preloaded h regs (A0..A5 u64x2,
// A6 u64). Same per-accumulator order as R13 -> bitwise-identical results.
#define MAC1(acc, W, A0, A1, A2, A3, A4, A5, A6)                              \
    FFMA2(acc, (A0).x, W##0);  FFMA2(acc, (A0).y, W##1);                      \
    FFMA2(acc, (A1).x, W##2);  FFMA2(acc, (A1).y, W##3);                      \
    FFMA2(acc, (A2).x, W##4);  FFMA2(acc, (A2).y, W##5);                      \
    FFMA2(acc, (A3).x, W##6);  FFMA2(acc, (A3).y, W##7);                      \
    FFMA2(acc, (A4).x, W##8);  FFMA2(acc, (A4).y, W##9);                      \
    FFMA2(acc, (A5).x, W##10); FFMA2(acc, (A5).y, W##11);                     \
    FFMA2(acc, (A6),   W##12);

// One LSTM timestep for both batches. SCHEDULE vs R13: gate order is
// g -> o -> i -> f; tanh(g) and sigmoid(o) MUFUs are launched before the
// i/f MAC block, which hides both 16-cycle MUFU latencies. Per-accumulator
// arithmetic order unchanged (bitwise-identical output).
#define LSTM_STEP(B0, B1, XV0, XV1) do {                                      \
    if (lane < 28) { (B0)[lane] = h0; (B1)[lane] = h1; }                      \
    __syncwarp();                                                             \
    ulonglong2 A0 = *reinterpret_cast<const ulonglong2*>((B0) + 0);           \
    ulonglong2 A1 = *reinterpret_cast<const ulonglong2*>((B0) + 4);           \
    ulonglong2 A2 = *reinterpret_cast<const ulonglong2*>((B0) + 8);           \
    ulonglong2 A3 = *reinterpret_cast<const ulonglong2*>((B0) + 12);          \
    ulonglong2 A4 = *reinterpret_cast<const ulonglong2*>((B0) + 16);          \
    ulonglong2 A5 = *reinterpret_cast<const ulonglong2*>((B0) + 20);          \
    u64        A6 = *reinterpret_cast<const u64*>((B0) + 24);                 \
    ulonglong2 C0 = *reinterpret_cast<const ulonglong2*>((B1) + 0);           \
    ulonglong2 C1 = *reinterpret_cast<const ulonglong2*>((B1) + 4);           \
    ulonglong2 C2 = *reinterpret_cast<const ulonglong2*>((B1) + 8);           \
    ulonglong2 C3 = *reinterpret_cast<const ulonglong2*>((B1) + 12);          \
    ulonglong2 C4 = *reinterpret_cast<const ulonglong2*>((B1) + 16);          \
    ulonglong2 C5 = *reinterpret_cast<const ulonglong2*>((B1) + 20);          \
    u64        C6 = *reinterpret_cast<const u64*>((B1) + 24);                 \
    /* g-gate first: longest tail chain */                                    \
    u64 ag0 = pack2(fmaf((XV0), wih_g, bias_g), 0.f);                         \
    u64 ag1 = pack2(fmaf((XV1), wih_g, bias_g), 0.f);                         \
    MAC1(ag0, wg, A0, A1, A2, A3, A4, A5, A6)                                 \
    MAC1(ag1, wg, C0, C1, C2, C3, C4, C5, C6)                                 \
    float gg0 = tanh_ap(unpack_sum(ag0));   /* MUFU in flight ... */          \
    float gg1 = tanh_ap(unpack_sum(ag1));                                     \
    /* o-gate second: its sigmoid also hides under the i/f MACs */            \
    u64 ao0 = pack2(fmaf((XV0), wih_o, bias_o), 0.f);                         \
    u64 ao1 = pack2(fmaf((XV1), wih_o, bias_o), 0.f);                         \
    MAC1(ao0, wo, A0, A1, A2, A3, A4, A5, A6)                                 \
    MAC1(ao1, wo, C0, C1, C2, C3, C4, C5, C6)                                 \
    float og0 = sig_ps(unpack_sum(ao0));    /* MUFU in flight ... */          \
    float og1 = sig_ps(unpack_sum(ao1));                                      \
    /* ... while i/f MACs execute */                                          \
    u64 ai0 = pack2(fmaf((XV0), wih_i, bias_i), 0.f);                         \
    u64 af0 = pack2(fmaf((XV0), wih_f, bias_f), 0.f);                         \
    u64 ai1 = pack2(fmaf((XV1), wih_i, bias_i), 0.f);                         \
    u64 af1 = pack2(fmaf((XV1), wih_f, bias_f), 0.f);                         \
    MAC1(ai0, wi, A0, A1, A2, A3, A4, A5, A6)                                 \
    MAC1(af0, wf, A0, A1, A2, A3, A4, A5, A6)                                 \
    MAC1(ai1, wi, C0, C1, C2, C3, C4, C5, C6)                                 \
    MAC1(af1, wf, C0, C1, C2, C3, C4, C5, C6)                                 \
    float ig = sig_ps(unpack_sum(ai0));                                       \
    float fg = sig_ps(unpack_sum(af0));                                       \
    c0 = fmaf(fg, c0, ig * gg0);  h0 = og0 * tanh_ap(c0);                     \
    ig = sig_ps(unpack_sum(ai1));                                             \
    fg = sig_ps(unpack_sum(af1));                                             \
    c1 = fmaf(fg, c1, ig * gg1);  h1 = og1 * tanh_ap(c1);                     \
} while (0)

__global__ void __launch_bounds__(BLK) lstm_kernel(
    const float* __restrict__ x,      // [B, T, 1]
    const float* __restrict__ W_ih,   // [4H, 1]
    const float* __restrict__ W_hh,   // [4H, H]
    const float* __restrict__ b_ih,   // [4H]
    const float* __restrict__ b_hh,   // [4H]
    const float* __restrict__ W_fc,   // [2, H]
    const float* __restrict__ b_fc,   // [2]
    float* __restrict__ out,          // [B, 2]
    int B)
{
    // h-broadcast buffers: [warp][parity][batch][28 units] (pads written as 0
    // by lanes 25-27, whose zero weights/biases keep their h exactly 0).
    __shared__ __align__(16) float hb[WPB][2][2][28];

    const int lane = threadIdx.x & 31;
    const int wIn  = threadIdx.x >> 5;
    const int warpGlobal = (blockIdx.x * BLK + threadIdx.x) >> 5;

    const bool lv = (lane < H);
    const int  jc = lv ? lane : (H - 1);

    int b0 = 2 * warpGlobal;
    int b1 = 2 * warpGlobal + 1;
    const bool v0 = (b0 < B), v1 = (b1 < B);
    if (!v0) b0 = B - 1;
    if (!v1) b1 = B - 1;

    // K-packed recurrent weights: 52 named u64 SSA values (cannot be demoted).
    R13(DECL_WP)
    R13(LOAD_WP)

    // x-projection weights & biases; i/f/o prescaled by 0.5 (exact).
    const float wih_i = lv ? 0.5f * __ldg(&W_ih[0 * H + jc]) : 0.f;
    const float wih_f = lv ? 0.5f * __ldg(&W_ih[1 * H + jc]) : 0.f;
    const float wih_g = lv ?        __ldg(&W_ih[2 * H + jc]) : 0.f;
    const float wih_o = lv ? 0.5f * __ldg(&W_ih[3 * H + jc]) : 0.f;
    const float bias_i = lv ? 0.5f * (__ldg(&b_ih[0 * H + jc]) + __ldg(&b_hh[0 * H + jc])) : 0.f;
    const float bias_f = lv ? 0.5f * (__ldg(&b_ih[1 * H + jc]) + __ldg(&b_hh[1 * H + jc])) : 0.f;
    const float bias_g = lv ?        (__ldg(&b_ih[2 * H + jc]) + __ldg(&b_hh[2 * H + jc])) : 0.f;
    const float bias_o = lv ? 0.5f * (__ldg(&b_ih[3 * H + jc]) + __ldg(&b_hh[3 * H + jc])) : 0.f;

    float* bA0 = &hb[wIn][0][0][0];
    float* bA1 = &hb[wIn][0][1][0];
    float* bB0 = &hb[wIn][1][0][0];
    float* bB1 = &hb[wIn][1][1][0];

    float h0 = 0.f, c0 = 0.f, h1 = 0.f, c1 = 0.f;

    const float4* xq0p = reinterpret_cast<const float4*>(x + (size_t)b0 * T_STEPS);
    const float4* xq1p = reinterpret_cast<const float4*>(x + (size_t)b1 * T_STEPS);

#pragma unroll 1
    for (int t4 = 0; t4 < T_STEPS / 4; t4++) {
        float4 xq0 = __ldg(xq0p + t4);   // warp-uniform broadcast loads
        float4 xq1 = __ldg(xq1p + t4);
        LSTM_STEP(bA0, bA1, xq0.x, xq1.x);
        LSTM_STEP(bB0, bB1, xq0.y, xq1.y);
        LSTM_STEP(bA0, bA1, xq0.z, xq1.z);
        LSTM_STEP(bB0, bB1, xq0.w, xq1.w);
    }

    // FC head: warp-reduce h . W_fc^T (idle lanes contribute h=0)
    const float wfc0 = lv ? __ldg(&W_fc[jc])     : 0.f;
    const float wfc1 = lv ? __ldg(&W_fc[H + jc]) : 0.f;
    float s00 = h0 * wfc0, s01 = h0 * wfc1;
    float s10 = h1 * wfc0, s11 = h1 * wfc1;
#pragma unroll
    for (int off = 16; off > 0; off >>= 1) {
        s00 += __shfl_xor_sync(0xffffffffu, s00, off);
        s01 += __shfl_xor_sync(0xffffffffu, s01, off);
        s10 += __shfl_xor_sync(0xffffffffu, s10, off);
        s11 += __shfl_xor_sync(0xffffffffu, s11, off);
    }
    if (lane == 0) {
        const float bf0 = __ldg(&b_fc[0]), bf1 = __ldg(&b_fc[1]);
        if (v0) {
            out[(size_t)b0 * 2 + 0] = s00 + bf0;
            out[(size_t)b0 * 2 + 1] = s01 + bf1;
        }
        if (v1) {
            out[(size_t)b1 * 2 + 0] = s10 + bf0;
            out[(size_t)b1 * 2 + 1] = s11 + bf1;
        }
    }
}

extern "C" void kernel_launch(void* const* d_in, const int* in_sizes, int n_in,
                              void* d_out, int out_size) {
    const float* x    = (const float*)d_in[0];
    const float* W_ih = (const float*)d_in[1];
    const float* W_hh = (const float*)d_in[2];
    const float* b_ih = (const float*)d_in[3];
    const float* b_hh = (const float*)d_in[4];
    const float* W_fc = (const float*)d_in[5];
    const float* b_fc = (const float*)d_in[6];

    int B = in_sizes[0] / T_STEPS;          // x is [B, T, 1]
    int warpsNeeded = (B + 1) / 2;          // 2 batches per warp
    int blocks      = (warpsNeeded * 32 + BLK - 1) / BLK;

    lstm_kernel<<<blocks, BLK>>>(x, W_ih, W_hh, b_ih, b_hh, W_fc, b_fc,
                                 (float*)d_out, B);
}

// round 17
// speedup vs baseline: 12.4973x; 1.0015x over previous
#include <cuda_runtime.h>

#define T_STEPS 240
#define H       25
#define BLK     128
#define WPB     (BLK / 32)

typedef unsigned long long u64;

// ---------------------------------------------------------------------------
// Packed f32x2 helpers (Blackwell)
// ---------------------------------------------------------------------------
__device__ __forceinline__ u64 pack2(float lo, float hi) {
    u64 r;
    asm("mov.b64 %0, {%1, %2};" : "=l"(r) : "f"(lo), "f"(hi));
    return r;
}
__device__ __forceinline__ float unpack_sum(u64 v) {
    float lo, hi;
    asm("mov.b64 {%0, %1}, %2;" : "=f"(lo), "=f"(hi) : "l"(v));
    return lo + hi;
}
#define FFMA2(acc, h, w) \
    asm("fma.rn.f32x2 %0, %1, %2, %0;" : "+l"(acc) : "l"(h), "l"(w))

// Compiler-only ordering fence: pins STS -> LDS program order without the
// ~23-cycle WARPSYNC. Valid because the loop body is branch-free (single PC
// per warp; the LSU processes a warp's smem ops in program order).
#define CFENCE() asm volatile("" ::: "memory")

// ---------------------------------------------------------------------------
// Hardware tanh (single MUFU). Sigmoid gates use PRESCALED weights (x0.5
// folded into W/bias at load): sigmoid(v) = fma(tanh(v_scaled), .5, .5).
// ---------------------------------------------------------------------------
__device__ __forceinline__ float tanh_ap(float x) {
    float y;
    asm("tanh.approx.f32 %0, %1;" : "=f"(y) : "f"(x));
    return y;
}
__device__ __forceinline__ float sig_ps(float v_scaled) {
    return fmaf(tanh_ap(v_scaled), 0.5f, 0.5f);
}

// Packed-k indices 0..12 (k pairs (0,1)..(24,25); k=25 padded to 0)
#define R13(M) M(0) M(1) M(2) M(3) M(4) M(5) M(6) M(7) M(8) M(9) M(10) M(11) M(12)

#define DECL_WP(Q) u64 wi##Q, wf##Q, wg##Q, wo##Q;

// Gate scale: i,f,o rows x0.5 (sigmoid prescale, exact); g row x1.
#define LOAD_WP(Q) {                                                          \
    const int k0 = 2 * (Q), k1 = 2 * (Q) + 1;                                 \
    float a, b;                                                               \
    a = (lv && k0 < H) ? 0.5f * __ldg(&W_hh[(0 * H + jc) * H + k0]) : 0.f;    \
    b = (lv && k1 < H) ? 0.5f * __ldg(&W_hh[(0 * H + jc) * H + k1]) : 0.f;    \
    wi##Q = pack2(a, b);                                                      \
    a = (lv && k0 < H) ? 0.5f * __ldg(&W_hh[(1 * H + jc) * H + k0]) : 0.f;    \
    b = (lv && k1 < H) ? 0.5f * __ldg(&W_hh[(1 * H + jc) * H + k1]) : 0.f;    \
    wf##Q = pack2(a, b);                                                      \
    a = (lv && k0 < H) ? __ldg(&W_hh[(2 * H + jc) * H + k0]) : 0.f;           \
    b = (lv && k1 < H) ? __ldg(&W_hh[(2 * H + jc) * H + k1]) : 0.f;           \
    wg##Q = pack2(a, b);                                                      \
    a = (lv && k0 < H) ? 0.5f * __ldg(&W_hh[(3 * H + jc) * H + k0]) : 0.f;    \
    b = (lv && k1 < H) ? 0.5f * __ldg(&W_hh[(3 * H + jc) * H + k1]) : 0.f;    \
    wo##Q = pack2(a, b);                                                      \
}

// Full 13-pair MAC for one accumulator from preloaded h regs (A0..A5 u64x2,
// A6 u64). Same per-accumulator order as R13 -> bitwise-identical results.
#define MAC1(acc, W, A0, A1, A2, A3, A4, A5, A6)                              \
    FFMA2(acc, (A0).x, W##0);  FFMA2(acc, (A0).y, W##1);                      \
    FFMA2(acc, (A1).x, W##2);  FFMA2(acc, (A1).y, W##3);                      \
    FFMA2(acc, (A2).x, W##4);  FFMA2(acc, (A2).y, W##5);                      \
    FFMA2(acc, (A3).x, W##6);  FFMA2(acc, (A3).y, W##7);                      \
    FFMA2(acc, (A4).x, W##8);  FFMA2(acc, (A4).y, W##9);                      \
    FFMA2(acc, (A5).x, W##10); FFMA2(acc, (A5).y, W##11);                     \
    FFMA2(acc, (A6),   W##12);

// One LSTM timestep for both batches. Schedule: g -> o -> i -> f with the
// g/o MUFUs hidden under the i/f MAC block (R16). Sync replaced by CFENCE.
#define LSTM_STEP(B0, B1, XV0, XV1) do {                                      \
    if (lane < 28) { (B0)[lane] = h0; (B1)[lane] = h1; }                      \
    CFENCE();                                                                 \
    ulonglong2 A0 = *reinterpret_cast<const ulonglong2*>((B0) + 0);           \
    ulonglong2 A1 = *reinterpret_cast<const ulonglong2*>((B0) + 4);           \
    ulonglong2 A2 = *reinterpret_cast<const ulonglong2*>((B0) + 8);           \
    ulonglong2 A3 = *reinterpret_cast<const ulonglong2*>((B0) + 12);          \
    ulonglong2 A4 = *reinterpret_cast<const ulonglong2*>((B0) + 16);          \
    ulonglong2 A5 = *reinterpret_cast<const ulonglong2*>((B0) + 20);          \
    u64        A6 = *reinterpret_cast<const u64*>((B0) + 24);                 \
    ulonglong2 C0 = *reinterpret_cast<const ulonglong2*>((B1) + 0);           \
    ulonglong2 C1 = *reinterpret_cast<const ulonglong2*>((B1) + 4);           \
    ulonglong2 C2 = *reinterpret_cast<const ulonglong2*>((B1) + 8);           \
    ulonglong2 C3 = *reinterpret_cast<const ulonglong2*>((B1) + 12);          \
    ulonglong2 C4 = *reinterpret_cast<const ulonglong2*>((B1) + 16);          \
    ulonglong2 C5 = *reinterpret_cast<const ulonglong2*>((B1) + 20);          \
    u64        C6 = *reinterpret_cast<const u64*>((B1) + 24);                 \
    /* g-gate first: longest tail chain */                                    \
    u64 ag0 = pack2(fmaf((XV0), wih_g, bias_g), 0.f);                         \
    u64 ag1 = pack2(fmaf((XV1), wih_g, bias_g), 0.f);                         \
    MAC1(ag0, wg, A0, A1, A2, A3, A4, A5, A6)                                 \
    MAC1(ag1, wg, C0, C1, C2, C3, C4, C5, C6)                                 \
    float gg0 = tanh_ap(unpack_sum(ag0));   /* MUFU in flight ... */          \
    float gg1 = tanh_ap(unpack_sum(ag1));                                     \
    /* o-gate second: its sigmoid also hides under the i/f MACs */            \
    u64 ao0 = pack2(fmaf((XV0), wih_o, bias_o), 0.f);                         \
    u64 ao1 = pack2(fmaf((XV1), wih_o, bias_o), 0.f);                         \
    MAC1(ao0, wo, A0, A1, A2, A3, A4, A5, A6)                                 \
    MAC1(ao1, wo, C0, C1, C2, C3, C4, C5, C6)                                 \
    float og0 = sig_ps(unpack_sum(ao0));    /* MUFU in flight ... */          \
    float og1 = sig_ps(unpack_sum(ao1));                                      \
    /* ... while i/f MACs execute */                                          \
    u64 ai0 = pack2(fmaf((XV0), wih_i, bias_i), 0.f);                         \
    u64 af0 = pack2(fmaf((XV0), wih_f, bias_f), 0.f);                         \
    u64 ai1 = pack2(fmaf((XV1), wih_i, bias_i), 0.f);                         \
    u64 af1 = pack2(fmaf((XV1), wih_f, bias_f), 0.f);                         \
    MAC1(ai0, wi, A0, A1, A2, A3, A4, A5, A6)                                 \
    MAC1(af0, wf, A0, A1, A2, A3, A4, A5, A6)                                 \
    MAC1(ai1, wi, C0, C1, C2, C3, C4, C5, C6)                                 \
    MAC1(af1, wf, C0, C1, C2, C3, C4, C5, C6)                                 \
    float ig = sig_ps(unpack_sum(ai0));                                       \
    float fg = sig_ps(unpack_sum(af0));                                       \
    c0 = fmaf(fg, c0, ig * gg0);  h0 = og0 * tanh_ap(c0);                     \
    ig = sig_ps(unpack_sum(ai1));                                             \
    fg = sig_ps(unpack_sum(af1));                                             \
    c1 = fmaf(fg, c1, ig * gg1);  h1 = og1 * tanh_ap(c1);                     \
} while (0)

__global__ void __launch_bounds__(BLK) lstm_kernel(
    const float* __restrict__ x,      // [B, T, 1]
    const float* __restrict__ W_ih,   // [4H, 1]
    const float* __restrict__ W_hh,   // [4H, H]
    const float* __restrict__ b_ih,   // [4H]
    const float* __restrict__ b_hh,   // [4H]
    const float* __restrict__ W_fc,   // [2, H]
    const float* __restrict__ b_fc,   // [2]
    float* __restrict__ out,          // [B, 2]
    int B)
{
    // h-broadcast buffers: [warp][parity][batch][28 units] (pads written as 0
    // by lanes 25-27, whose zero weights/biases keep their h exactly 0).
    __shared__ __align__(16) float hb[WPB][2][2][28];

    const int lane = threadIdx.x & 31;
    const int wIn  = threadIdx.x >> 5;
    const int warpGlobal = (blockIdx.x * BLK + threadIdx.x) >> 5;

    const bool lv = (lane < H);
    const int  jc = lv ? lane : (H - 1);

    int b0 = 2 * warpGlobal;
    int b1 = 2 * warpGlobal + 1;
    const bool v0 = (b0 < B), v1 = (b1 < B);
    if (!v0) b0 = B - 1;
    if (!v1) b1 = B - 1;

    // K-packed recurrent weights: 52 named u64 SSA values (cannot be demoted).
    R13(DECL_WP)
    R13(LOAD_WP)

    // x-projection weights & biases; i/f/o prescaled by 0.5 (exact).
    const float wih_i = lv ? 0.5f * __ldg(&W_ih[0 * H + jc]) : 0.f;
    const float wih_f = lv ? 0.5f * __ldg(&W_ih[1 * H + jc]) : 0.f;
    const float wih_g = lv ?        __ldg(&W_ih[2 * H + jc]) : 0.f;
    const float wih_o = lv ? 0.5f * __ldg(&W_ih[3 * H + jc]) : 0.f;
    const float bias_i = lv ? 0.5f * (__ldg(&b_ih[0 * H + jc]) + __ldg(&b_hh[0 * H + jc])) : 0.f;
    const float bias_f = lv ? 0.5f * (__ldg(&b_ih[1 * H + jc]) + __ldg(&b_hh[1 * H + jc])) : 0.f;
    const float bias_g = lv ?        (__ldg(&b_ih[2 * H + jc]) + __ldg(&b_hh[2 * H + jc])) : 0.f;
    const float bias_o = lv ? 0.5f * (__ldg(&b_ih[3 * H + jc]) + __ldg(&b_hh[3 * H + jc])) : 0.f;

    float* bA0 = &hb[wIn][0][0][0];
    float* bA1 = &hb[wIn][0][1][0];
    float* bB0 = &hb[wIn][1][0][0];
    float* bB1 = &hb[wIn][1][1][0];

    float h0 = 0.f, c0 = 0.f, h1 = 0.f, c1 = 0.f;

    const float4* xq0p = reinterpret_cast<const float4*>(x + (size_t)b0 * T_STEPS);
    const float4* xq1p = reinterpret_cast<const float4*>(x + (size_t)b1 * T_STEPS);

#pragma unroll 1
    for (int t4 = 0; t4 < T_STEPS / 4; t4++) {
        float4 xq0 = __ldg(xq0p + t4);   // warp-uniform broadcast loads
        float4 xq1 = __ldg(xq1p + t4);
        LSTM_STEP(bA0, bA1, xq0.x, xq1.x);
        LSTM_STEP(bB0, bB1, xq0.y, xq1.y);
        LSTM_STEP(bA0, bA1, xq0.z, xq1.z);
        LSTM_STEP(bB0, bB1, xq0.w, xq1.w);
    }

    // FC head: warp-reduce h . W_fc^T (idle lanes contribute h=0)
    const float wfc0 = lv ? __ldg(&W_fc[jc])     : 0.f;
    const float wfc1 = lv ? __ldg(&W_fc[H + jc]) : 0.f;
    float s00 = h0 * wfc0, s01 = h0 * wfc1;
    float s10 = h1 * wfc0, s11 = h1 * wfc1;
#pragma unroll
    for (int off = 16; off > 0; off >>= 1) {
        s00 += __shfl_xor_sync(0xffffffffu, s00, off);
        s01 += __shfl_xor_sync(0xffffffffu, s01, off);
        s10 += __shfl_xor_sync(0xffffffffu, s10, off);
        s11 += __shfl_xor_sync(0xffffffffu, s11, off);
    }
    if (lane == 0) {
        const float bf0 = __ldg(&b_fc[0]), bf1 = __ldg(&b_fc[1]);
        if (v0) {
            out[(size_t)b0 * 2 + 0] = s00 + bf0;
            out[(size_t)b0 * 2 + 1] = s01 + bf1;
        }
        if (v1) {
            out[(size_t)b1 * 2 + 0] = s10 + bf0;
            out[(size_t)b1 * 2 + 1] = s11 + bf1;
        }
    }
}

extern "C" void kernel_launch(void* const* d_in, const int* in_sizes, int n_in,
                              void* d_out, int out_size) {
    const float* x    = (const float*)d_in[0];
    const float* W_ih = (const float*)d_in[1];
    const float* W_hh = (const float*)d_in[2];
    const float* b_ih = (const float*)d_in[3];
    const float* b_hh = (const float*)d_in[4];
    const float* W_fc = (const float*)d_in[5];
    const float* b_fc = (const float*)d_in[6];

    int B = in_sizes[0] / T_STEPS;          // x is [B, T, 1]
    int warpsNeeded = (B + 1) / 2;          // 2 batches per warp
    int blocks      = (warpsNeeded * 32 + BLK - 1) / BLK;

    lstm_kernel<<<blocks, BLK>>>(x, W_ih, W_hh, b_ih, b_hh, W_fc, b_fc,
                                 (float*)d_out, B);
}